// round 2
// baseline (speedup 1.0000x reference)
#include <cuda_runtime.h>
#include <cuda_bf16.h>
#include <cstddef>

// RandCropResize via per-block shared staging.
// Block = (output row h, batch b), 512 threads along w.
// Vertical taps (ay0, ay1, wy) are uniform per block, so the staging phase
// loads the two source rows with coalesced float4 LDGs and fuses the
// y-interpolation into shared memory. The main phase is then a 1-D
// horizontal lerp per output pixel: 6 LDS + 3 FMA + 3 coalesced STG.

#define IMG_H 512
#define IMG_W 512
#define IMG_C 3
#define SPITCH 520   // smem row pitch in floats (multiple of 8: STS.128-aligned, no conflicts)

__global__ void __launch_bounds__(512, 4)
rand_crop_resize_kernel(const float* __restrict__ img,
                        const int* __restrict__ y1v,
                        const int* __restrict__ y2v,
                        const int* __restrict__ x1v,
                        const int* __restrict__ x2v,
                        float* __restrict__ out)
{
    __shared__ float srow[IMG_C * SPITCH];   // y-interpolated source rows

    const int h   = blockIdx.x;
    const int b   = blockIdx.y;
    const int tid = threadIdx.x;

    const int Y1 = y1v[b], Y2 = y2v[b];
    const int X1 = x1v[b], X2 = x2v[b];

    // ---- vertical coords: uniform across the block ----
    const int   ncy = Y2 - Y1;
    const float ny  = (float)ncy;
    float sy = ((float)h + 0.5f) * ny * (1.0f / (float)IMG_H) - 0.5f;
    sy = fminf(fmaxf(sy, 0.0f), ny - 1.0f);
    const int   iy0 = (int)floorf(sy);
    const int   iy1 = min(iy0 + 1, ncy - 1);
    const float wy  = sy - (float)iy0;
    const int   ay0 = Y1 + iy0;
    const int   ay1 = Y1 + iy1;

    // ---- x staging span: [xlo, xhi4) covers all taps, float4-aligned ----
    const int xlo   = X1 & ~3;
    const int xhi4  = (X2 + 3) & ~3;         // <= 512 since X2 <= 512
    const int span4 = (xhi4 - xlo) >> 2;     // float4 count per row

    const size_t img_stride = (size_t)IMG_H * IMG_W;
    const float* base = img + (size_t)b * IMG_C * img_stride;

    // ---- staging: load 2 rows x 3 channels, fuse y-lerp, store to smem ----
    const int nitems = IMG_C * span4;
    for (int item = tid; item < nitems; item += 512) {
        const int c  = item / span4;
        const int xq = item - c * span4;
        const float* p = base + (size_t)c * img_stride + xlo + (xq << 2);
        const float4 v0 = *(const float4*)(p + (size_t)ay0 * IMG_W);
        const float4 v1 = *(const float4*)(p + (size_t)ay1 * IMG_W);
        float4 f;
        f.x = v0.x + (v1.x - v0.x) * wy;
        f.y = v0.y + (v1.y - v0.y) * wy;
        f.z = v0.z + (v1.z - v0.z) * wy;
        f.w = v0.w + (v1.w - v0.w) * wy;
        *(float4*)(&srow[c * SPITCH + (xq << 2)]) = f;
    }
    __syncthreads();

    // ---- main: horizontal lerp per output pixel ----
    const int   w   = tid;
    const int   ncx = X2 - X1;
    const float nx  = (float)ncx;
    float sx = ((float)w + 0.5f) * nx * (1.0f / (float)IMG_W) - 0.5f;
    sx = fminf(fmaxf(sx, 0.0f), nx - 1.0f);
    const int   ix0 = (int)floorf(sx);
    const int   ix1 = min(ix0 + 1, ncx - 1);
    const float wx  = sx - (float)ix0;
    const int   l0  = (X1 + ix0) - xlo;      // smem-relative tap indices
    const int   l1  = (X1 + ix1) - xlo;

    float* obase = out + (size_t)b * IMG_C * img_stride
                       + (size_t)h * IMG_W + w;
#pragma unroll
    for (int c = 0; c < IMG_C; c++) {
        const float f0 = srow[c * SPITCH + l0];
        const float f1 = srow[c * SPITCH + l1];
        obase[(size_t)c * img_stride] = f0 + (f1 - f0) * wx;
    }
}

extern "C" void kernel_launch(void* const* d_in, const int* in_sizes, int n_in,
                              void* d_out, int out_size)
{
    const float* img = (const float*)d_in[0];
    const int*   y1  = (const int*)d_in[1];
    const int*   y2  = (const int*)d_in[2];
    const int*   x1  = (const int*)d_in[3];
    const int*   x2  = (const int*)d_in[4];
    float*       out = (float*)d_out;

    dim3 grid(IMG_H, 64);   // (h, b)
    dim3 block(IMG_W);
    rand_crop_resize_kernel<<<grid, block>>>(img, y1, y2, x1, x2, out);
}